// round 8
// baseline (speedup 1.0000x reference)
#include <cuda_runtime.h>
#include <math.h>
#include <stdint.h>

#define HEADS 8
#define DHK 8
#define DHV 16
#define DIM 128
#define INC 128
#define EPS 1e-5f
#define QSCALE 0.08838834764831845f   // 128^-0.5

typedef unsigned long long ull;

__device__ float g_qkv[2048 * 32768];   // [b][h][r(0..31)][d]

__device__ __forceinline__ ull pk2(float a, float b) {
    ull r; asm("mov.b64 %0, {%1, %2};" : "=l"(r) : "f"(a), "f"(b)); return r;
}
__device__ __forceinline__ void upk2(ull v, float& a, float& b) {
    asm("mov.b64 {%0, %1}, %2;" : "=f"(a), "=f"(b) : "l"(v));
}
__device__ __forceinline__ ull fma2(ull a, ull b, ull c) {
    ull r; asm("fma.rn.f32x2 %0, %1, %2, %3;" : "=l"(r) : "l"(a), "l"(b), "l"(c));
    return r;
}
__device__ __forceinline__ ull add2(ull a, ull b) {
    ull r; asm("add.rn.f32x2 %0, %1, %2;" : "=l"(r) : "l"(a), "l"(b));
    return r;
}
__device__ __forceinline__ uint32_t f2tf32(float f) {
    uint32_t r; asm("cvt.rna.tf32.f32 %0, %1;" : "=r"(r) : "f"(f)); return r;
}
__device__ __forceinline__ void split_tf32(float f, uint32_t& hi, uint32_t& lo) {
    hi = f2tf32(f);
    lo = f2tf32(f - __uint_as_float(hi));
}
__device__ __forceinline__ void mma_tf32(float* c, const uint32_t* a, const uint32_t* b) {
    asm volatile(
        "mma.sync.aligned.m16n8k8.row.col.f32.tf32.tf32.f32 "
        "{%0,%1,%2,%3}, {%4,%5,%6,%7}, {%8,%9}, {%0,%1,%2,%3};"
        : "+f"(c[0]), "+f"(c[1]), "+f"(c[2]), "+f"(c[3])
        : "r"(a[0]), "r"(a[1]), "r"(a[2]), "r"(a[3]), "r"(b[0]), "r"(b[1]));
}

// ============================================================================
// Kernel A: conv1x1 + BN via mma.sync tf32 (unchanged, round-7 verified)
// ============================================================================
#define CA_STR 132
#define CB_STR 136
#define CV_BS  (128 * CA_STR)
#define CV_IV  (CV_BS + 128 * CB_STR)
#define CV_BB  (CV_IV + 128)
#define CV_TOT (CV_BB + 128)

__global__ void __launch_bounds__(256, 1)
conv_bn_mma_kernel(const float* __restrict__ x, const float* __restrict__ W,
                   const float* __restrict__ gamma, const float* __restrict__ beta,
                   const float* __restrict__ mean, const float* __restrict__ var,
                   float* __restrict__ qkv)
{
    extern __shared__ float sm[];
    float* As  = sm;
    float* Bs  = sm + CV_BS;
    float* ivs = sm + CV_IV;
    float* bss = sm + CV_BB;

    const int t      = threadIdx.x;
    const int b      = blockIdx.x >> 1;
    const int o_base = (blockIdx.x & 1) * 128;

#pragma unroll
    for (int it = 0; it < 16; ++it) {
        int e  = t + 256 * it;
        int o  = e >> 5;
        int c4 = (e & 31) * 4;
        float4 wv = *reinterpret_cast<const float4*>(W + (o_base + o) * 128 + c4);
        float4 s;
        s.x = __uint_as_float(f2tf32(wv.x));
        s.y = __uint_as_float(f2tf32(wv.y));
        s.z = __uint_as_float(f2tf32(wv.z));
        s.w = __uint_as_float(f2tf32(wv.w));
        *reinterpret_cast<float4*>(As + o * CA_STR + c4) = s;
    }
#pragma unroll
    for (int it = 0; it < 16; ++it) {
        int e  = t + 256 * it;
        int c  = e >> 5;
        int d4 = (e & 31) * 4;
        float4 xv = *reinterpret_cast<const float4*>(x + (size_t)b * 16384 + c * 128 + d4);
        float4 s;
        s.x = __uint_as_float(f2tf32(xv.x));
        s.y = __uint_as_float(f2tf32(xv.y));
        s.z = __uint_as_float(f2tf32(xv.z));
        s.w = __uint_as_float(f2tf32(xv.w));
        *reinterpret_cast<float4*>(Bs + c * CB_STR + d4) = s;
    }
    if (t < 128) {
        int o = o_base + t;
        float iv   = gamma[o] * rsqrtf(var[o] + EPS);
        float bias = beta[o] - mean[o] * iv;
        if (o < 64) { iv *= QSCALE; bias *= QSCALE; }
        ivs[t] = iv;
        bss[t] = bias;
    }
    __syncthreads();

    const int warp = t >> 5, lane = t & 31;
    const int wm = warp & 3, wn = warp >> 2;
    const int m0 = wm * 32, n0 = wn * 64;
    const int gp = lane >> 2, tid4 = lane & 3;

    float acc[16][4];
#pragma unroll
    for (int i = 0; i < 16; ++i)
#pragma unroll
        for (int p = 0; p < 4; ++p) acc[i][p] = 0.f;

#pragma unroll
    for (int s = 0; s < 16; ++s) {
        uint32_t a[2][4];
        const float* abase = As + s * 8 + tid4;
#pragma unroll
        for (int mt = 0; mt < 2; ++mt) {
            int r0 = m0 + mt * 16 + gp;
            a[mt][0] = __float_as_uint(abase[r0 * CA_STR]);
            a[mt][1] = __float_as_uint(abase[(r0 + 8) * CA_STR]);
            a[mt][2] = __float_as_uint(abase[r0 * CA_STR + 4]);
            a[mt][3] = __float_as_uint(abase[(r0 + 8) * CA_STR + 4]);
        }
        uint32_t bf[8][2];
        const float* bbase = Bs + (s * 8 + tid4) * CB_STR + n0 + gp;
#pragma unroll
        for (int nt = 0; nt < 8; ++nt) {
            bf[nt][0] = __float_as_uint(bbase[nt * 8]);
            bf[nt][1] = __float_as_uint(bbase[4 * CB_STR + nt * 8]);
        }
#pragma unroll
        for (int mt = 0; mt < 2; ++mt)
#pragma unroll
            for (int nt = 0; nt < 8; ++nt)
                mma_tf32(acc[mt * 8 + nt], a[mt], bf[nt]);
    }

#pragma unroll
    for (int mt = 0; mt < 2; ++mt) {
        int lr0 = m0 + mt * 16 + gp;
        int lr1 = lr0 + 8;
        float iv0 = ivs[lr0], bv0 = bss[lr0];
        float iv1 = ivs[lr1], bv1 = bss[lr1];
        int o0 = o_base + lr0, o1 = o_base + lr1;
        float* d00 = qkv + (size_t)b * 32768 + (o0 & 7) * 4096 + (o0 >> 3) * 128;
        float* d01 = qkv + (size_t)b * 32768 + (o1 & 7) * 4096 + (o1 >> 3) * 128;
#pragma unroll
        for (int nt = 0; nt < 8; ++nt) {
            int d = n0 + nt * 8 + 2 * tid4;
            const float* a4 = acc[mt * 8 + nt];
            float2 s0, s1;
            s0.x = a4[0] * iv0 + bv0; s0.y = a4[1] * iv0 + bv0;
            s1.x = a4[2] * iv1 + bv1; s1.y = a4[3] * iv1 + bv1;
            *reinterpret_cast<float2*>(d00 + d) = s0;
            *reinterpret_cast<float2*>(d01 + d) = s1;
        }
    }
}

// ============================================================================
// Kernel B: attention per (b, h)
// smem (floats):
//  q     [8][128]   @ 0     (kvred[16][128] aliases q+k after phase 1b)
//  k     [8][128]   @ 1024
//  v_ji  [128][17]  @ 2048  (v transposed [j][i], padded stride 17)
//  relqk [16][256]  @ 4224  (q_emb/k_emb; relv after phase 1a)
//  attnT [128][132] @ 8320
//  invs  [128]      @ 25216
// total 25344 floats = 101376 B -> 2 CTAs/SM
// ============================================================================
#define AT_STRIDE 132
#define SM_Q     0
#define SM_K     1024
#define SM_VJ    2048
#define SM_REL   4224
#define SM_ATT   8320
#define SM_INV   25216
#define SM_TOTAL 25344

__global__ void __launch_bounds__(256, 2)
attn_kernel(const float* __restrict__ qkv, const float* __restrict__ relative,
            float* __restrict__ out)
{
    extern __shared__ float sm[];
    float* q     = sm + SM_Q;
    float* k     = sm + SM_K;
    float* v_ji  = sm + SM_VJ;
    float* relqk = sm + SM_REL;
    float* attnT = sm + SM_ATT;
    float* invs  = sm + SM_INV;
    float* relv  = relqk;           // alias after 1a
    float* kvred = sm + SM_Q;       // alias q+k after 1b (16*128 floats)

    const int t    = threadIdx.x;
    const int bid  = blockIdx.x;
    const int b    = bid >> 3;
    const int h    = bid & 7;
    const int warp = t >> 5, lane = t & 31;
    const int gp   = lane >> 2, tid4 = lane & 3;

    // ---------------- phase 0: load q/k, v transposed, relqk -------------------
    {
        const float* src = qkv + (size_t)b * 32768 + h * 4096;
#pragma unroll
        for (int it = 0; it < 4; ++it) {
            int e4 = t + 256 * it;              // 0..1023
            int r  = e4 >> 5;
            int dw = (e4 & 31) * 4;
            float4 val = *reinterpret_cast<const float4*>(src + r * 128 + dw);
            if (r < 8) {
                *reinterpret_cast<float4*>(q + r * 128 + dw) = val;
            } else if (r < 16) {
                *reinterpret_cast<float4*>(k + (r - 8) * 128 + dw) = val;
            } else {
                int i = r - 16;
                v_ji[(dw + 0) * 17 + i] = val.x;
                v_ji[(dw + 1) * 17 + i] = val.y;
                v_ji[(dw + 2) * 17 + i] = val.z;
                v_ji[(dw + 3) * 17 + i] = val.w;
            }
        }
        for (int idx = t; idx < 16 * 255; idx += 256) {
            int c = idx / 255, m = idx - c * 255;
            relqk[c * 256 + m] = relative[idx];
        }
    }
    __syncthreads();

    // ---------------- phase 1a: Toeplitz qr + kr -> attnT (raw) -----------------
    {
        const int tx = t & 15, ty = t >> 4;
        const int d0 = tx * 8, j0 = ty * 8;
        const int base = d0 - j0 + 120;

        ull acc[8][4];
#pragma unroll
        for (int a = 0; a < 8; ++a)
#pragma unroll
            for (int p = 0; p < 4; ++p) acc[a][p] = 0ULL;

#pragma unroll 2
        for (int i = 0; i < 8; ++i) {
            const float* qi = q + i * 128;
            const float* ki = k + i * 128;
            ull qp[4], kp[4];
            {
                ulonglong2 a0 = *reinterpret_cast<const ulonglong2*>(qi + d0);
                ulonglong2 a1 = *reinterpret_cast<const ulonglong2*>(qi + d0 + 4);
                qp[0] = a0.x; qp[1] = a0.y; qp[2] = a1.x; qp[3] = a1.y;
                ulonglong2 b0 = *reinterpret_cast<const ulonglong2*>(ki + d0);
                ulonglong2 b1 = *reinterpret_cast<const ulonglong2*>(ki + d0 + 4);
                kp[0] = b0.x; kp[1] = b0.y; kp[2] = b1.x; kp[3] = b1.y;
            }
            // qr: q[i][d] * relq[i][d-j+127]
            {
                float wv[16];
                const float* rr = relqk + i * 256 + base;
#pragma unroll
                for (int u = 0; u < 4; ++u)
                    *reinterpret_cast<float4*>(wv + 4 * u) = *reinterpret_cast<const float4*>(rr + 4 * u);
                ull wo[7];
#pragma unroll
                for (int u = 0; u < 7; ++u) wo[u] = pk2(wv[2 * u + 1], wv[2 * u + 2]);
#pragma unroll
                for (int jj = 0; jj < 8; ++jj)
#pragma unroll
                    for (int p = 0; p < 4; ++p) {
                        const int a = 2 * p + 7 - jj;
                        ull pair = (a & 1) ? wo[a >> 1]
                                           : *reinterpret_cast<const ull*>(wv + a);
                        acc[jj][p] = fma2(qp[p], pair, acc[jj][p]);
                    }
            }
            // kr: k[i][d] * relk[i][d-j+127]
            {
                float wv[16];
                const float* rr = relqk + (8 + i) * 256 + base;
#pragma unroll
                for (int u = 0; u < 4; ++u)
                    *reinterpret_cast<float4*>(wv + 4 * u) = *reinterpret_cast<const float4*>(rr + 4 * u);
                ull wo[7];
#pragma unroll
                for (int u = 0; u < 7; ++u) wo[u] = pk2(wv[2 * u + 1], wv[2 * u + 2]);
#pragma unroll
                for (int jj = 0; jj < 8; ++jj)
#pragma unroll
                    for (int p = 0; p < 4; ++p) {
                        const int a = 2 * p + 7 - jj;
                        ull pair = (a & 1) ? wo[a >> 1]
                                           : *reinterpret_cast<const ull*>(wv + a);
                        acc[jj][p] = fma2(kp[p], pair, acc[jj][p]);
                    }
            }
        }
        // store raw qr+kr
#pragma unroll
        for (int jj = 0; jj < 8; ++jj) {
            float* dst = attnT + (j0 + jj) * AT_STRIDE + d0;
#pragma unroll
            for (int p = 0; p < 4; ++p)
                *reinterpret_cast<ull*>(dst + 2 * p) = acc[jj][p];
        }
    }
    __syncthreads();   // attnT (qr+kr) ready; relqk dead

    // ---------------- phase 1b: dots mma + exp + row sums; relv load ------------
    {
        const int m0 = warp * 16;
        // A = q^T fragments (split tf32): A[m=d][k=i] = q[i][d]
        uint32_t ah[4], al[4];
        split_tf32(q[tid4 * 128 + m0 + gp],           ah[0], al[0]);
        split_tf32(q[tid4 * 128 + m0 + gp + 8],       ah[1], al[1]);
        split_tf32(q[(tid4 + 4) * 128 + m0 + gp],     ah[2], al[2]);
        split_tf32(q[(tid4 + 4) * 128 + m0 + gp + 8], ah[3], al[3]);

        float s0 = 0.f, s1 = 0.f;
#pragma unroll
        for (int nt = 0; nt < 16; ++nt) {
            const int n0 = nt * 8;
            float c[4];
            c[0] = attnT[(n0 + 2 * tid4) * AT_STRIDE + m0 + gp];
            c[1] = attnT[(n0 + 2 * tid4 + 1) * AT_STRIDE + m0 + gp];
            c[2] = attnT[(n0 + 2 * tid4) * AT_STRIDE + m0 + gp + 8];
            c[3] = attnT[(n0 + 2 * tid4 + 1) * AT_STRIDE + m0 + gp + 8];
            // B[k=i][n=j] = k[i][j]
            uint32_t bh[2], bl[2];
            split_tf32(k[tid4 * 128 + n0 + gp],       bh[0], bl[0]);
            split_tf32(k[(tid4 + 4) * 128 + n0 + gp], bh[1], bl[1]);
            mma_tf32(c, ah, bh);
            mma_tf32(c, al, bh);
            mma_tf32(c, ah, bl);
            c[0] = __expf(c[0]); c[1] = __expf(c[1]);
            c[2] = __expf(c[2]); c[3] = __expf(c[3]);
            s0 += c[0] + c[1];
            s1 += c[2] + c[3];
            attnT[(n0 + 2 * tid4) * AT_STRIDE + m0 + gp]         = c[0];
            attnT[(n0 + 2 * tid4 + 1) * AT_STRIDE + m0 + gp]     = c[1];
            attnT[(n0 + 2 * tid4) * AT_STRIDE + m0 + gp + 8]     = c[2];
            attnT[(n0 + 2 * tid4 + 1) * AT_STRIDE + m0 + gp + 8] = c[3];
        }
        s0 += __shfl_xor_sync(0xffffffffu, s0, 1);
        s0 += __shfl_xor_sync(0xffffffffu, s0, 2);
        s1 += __shfl_xor_sync(0xffffffffu, s1, 1);
        s1 += __shfl_xor_sync(0xffffffffu, s1, 2);
        if (tid4 == 0) {
            invs[m0 + gp]     = 1.0f / s0;
            invs[m0 + gp + 8] = 1.0f / s1;
        }
        // relv load (relqk dead)
        for (int idx = t; idx < 16 * 255; idx += 256) {
            int c = idx / 255, m = idx - c * 255;
            relv[c * 256 + m] = relative[16 * 255 + idx];
        }
    }
    __syncthreads();   // exp'd attnT + invs + relv ready; q/k dead

    // ---------------- phase 3: kv Toeplitz (scalar, sliding window) -------------
    {
        const int i0  = (warp & 3) * 4;
        const int jh  = warp >> 2;
        const int d0  = lane * 4;
        const int jb0 = jh * 64;

        ull acc[4][2];
#pragma unroll
        for (int ii = 0; ii < 4; ++ii) { acc[ii][0] = 0ULL; acc[ii][1] = 0ULL; }

        ull we[4][3], wo[4][3];
        float lastf0[4];
#pragma unroll
        for (int ii = 0; ii < 4; ++ii) {
            const float* rp = relv + (i0 + ii) * 256 + (d0 - jb0 + 124);
            float4 lo4 = *reinterpret_cast<const float4*>(rp);
            float4 hi4 = *reinterpret_cast<const float4*>(rp + 4);
            we[ii][0] = pk2(lo4.x, lo4.y);
            we[ii][1] = pk2(lo4.z, lo4.w);
            we[ii][2] = pk2(hi4.x, hi4.y);
            wo[ii][0] = pk2(lo4.y, lo4.z);
            wo[ii][1] = pk2(lo4.w, hi4.x);
            wo[ii][2] = pk2(hi4.y, hi4.z);
            lastf0[ii] = lo4.x;
        }

        for (int g = 0; g < 16; ++g) {
            const int jb = jb0 + g * 4;
            if (g > 0) {
                const int baseg = d0 - jb + 124;
#pragma unroll
                for (int ii = 0; ii < 4; ++ii) {
                    we[ii][2] = we[ii][0];
                    wo[ii][2] = wo[ii][0];
                    float4 f = *reinterpret_cast<const float4*>(relv + (i0 + ii) * 256 + baseg);
                    we[ii][0] = pk2(f.x, f.y);
                    we[ii][1] = pk2(f.z, f.w);
                    wo[ii][0] = pk2(f.y, f.z);
                    wo[ii][1] = pk2(f.w, lastf0[ii]);
                    lastf0[ii] = f.x;
                }
            }
#pragma unroll
            for (int jj = 0; jj < 4; ++jj) {
                const int j = jb + jj;
                ulonglong2 at2 = *reinterpret_cast<const ulonglong2*>(attnT + j * AT_STRIDE + d0);
#pragma unroll
                for (int ii = 0; ii < 4; ++ii) {
                    const int o0 = 3 - jj;
                    const int o1 = 5 - jj;
                    ull pr0 = (o0 & 1) ? wo[ii][o0 >> 1] : we[ii][o0 >> 1];
                    ull pr1 = (o1 & 1) ? wo[ii][o1 >> 1] : we[ii][o1 >> 1];
                    acc[ii][0] = fma2(at2.x, pr0, acc[ii][0]);
                    acc[ii][1] = fma2(at2.y, pr1, acc[ii][1]);
                }
            }
        }

        ull* kvr = reinterpret_cast<ull*>(kvred);
        if (jh == 1) {
#pragma unroll
            for (int ii = 0; ii < 4; ++ii) {
                kvr[((i0 + ii) * 128 + d0) / 2]     = acc[ii][0];
                kvr[((i0 + ii) * 128 + d0) / 2 + 1] = acc[ii][1];
            }
        }
        __syncthreads();
        if (jh == 0) {
#pragma unroll
            for (int ii = 0; ii < 4; ++ii) {
                int base = ((i0 + ii) * 128 + d0) / 2;
                kvr[base]     = add2(acc[ii][0], kvr[base]);
                kvr[base + 1] = add2(acc[ii][1], kvr[base + 1]);
            }
        }
    }
    __syncthreads();   // kvred complete

    // ---------------- phase 4: out = attn . v via mma + combine -----------------
    {
        const int m0 = warp * 16;
        float c[2][4];
#pragma unroll
        for (int nt = 0; nt < 2; ++nt)
#pragma unroll
            for (int p = 0; p < 4; ++p) c[nt][p] = 0.f;

#pragma unroll
        for (int ks = 0; ks < 16; ++ks) {
            const int j0 = ks * 8;
            uint32_t ah[4], al[4];
            split_tf32(attnT[(j0 + tid4) * AT_STRIDE + m0 + gp],         ah[0], al[0]);
            split_tf32(attnT[(j0 + tid4) * AT_STRIDE + m0 + gp + 8],     ah[1], al[1]);
            split_tf32(attnT[(j0 + tid4 + 4) * AT_STRIDE + m0 + gp],     ah[2], al[2]);
            split_tf32(attnT[(j0 + tid4 + 4) * AT_STRIDE + m0 + gp + 8], ah[3], al[3]);
#pragma unroll
            for (int nt = 0; nt < 2; ++nt) {
                uint32_t bh[2], bl[2];
                split_tf32(v_ji[(j0 + tid4) * 17 + nt * 8 + gp],     bh[0], bl[0]);
                split_tf32(v_ji[(j0 + tid4 + 4) * 17 + nt * 8 + gp], bh[1], bl[1]);
                mma_tf32(c[nt], ah, bh);
                mma_tf32(c[nt], al, bh);
                mma_tf32(c[nt], ah, bl);
            }
        }

        const int dr0 = m0 + gp, dr1 = m0 + gp + 8;
        const float iv0 = invs[dr0], iv1 = invs[dr1];
        float* ob = out + (size_t)b * 16384 + h * 2048;
#pragma unroll
        for (int nt = 0; nt < 2; ++nt) {
            const int ib = nt * 8 + 2 * tid4;
            ob[ib * 128 + dr0]       = (c[nt][0] + kvred[ib * 128 + dr0])       * iv0;
            ob[(ib + 1) * 128 + dr0] = (c[nt][1] + kvred[(ib + 1) * 128 + dr0]) * iv0;
            ob[ib * 128 + dr1]       = (c[nt][2] + kvred[ib * 128 + dr1])       * iv1;
            ob[(ib + 1) * 128 + dr1] = (c[nt][3] + kvred[(ib + 1) * 128 + dr1]) * iv1;
        }
    }
}

// ============================================================================
extern "C" void kernel_launch(void* const* d_in, const int* in_sizes, int n_in,
                              void* d_out, int out_size) {
    const float* x        = (const float*)d_in[0];
    const float* W        = (const float*)d_in[1];
    const float* gamma    = (const float*)d_in[2];
    const float* beta     = (const float*)d_in[3];
    const float* mean     = (const float*)d_in[4];
    const float* var      = (const float*)d_in[5];
    const float* relative = (const float*)d_in[6];
    float* out = (float*)d_out;

    int nb = in_sizes[0] / (INC * DIM);

    float* scratch;
    cudaGetSymbolAddress((void**)&scratch, g_qkv);

    const int smemA = CV_TOT * (int)sizeof(float);     // 138240
    const int smemB = SM_TOTAL * (int)sizeof(float);   // 101376
    cudaFuncSetAttribute(conv_bn_mma_kernel, cudaFuncAttributeMaxDynamicSharedMemorySize, smemA);
    cudaFuncSetAttribute(attn_kernel,        cudaFuncAttributeMaxDynamicSharedMemorySize, smemB);

    conv_bn_mma_kernel<<<nb * 2, 256, smemA>>>(x, W, gamma, beta, mean, var, scratch);
    attn_kernel<<<nb * HEADS, 256, smemB>>>(scratch, relative, out);
}

// round 10
// speedup vs baseline: 1.0603x; 1.0603x over previous
#include <cuda_runtime.h>
#include <math.h>
#include <stdint.h>

#define HEADS 8
#define DIM 128
#define INC 128
#define EPS 1e-5f
#define QSCALE 0.08838834764831845f   // 128^-0.5

typedef unsigned long long ull;

__device__ __forceinline__ ull pk2(float a, float b) {
    ull r; asm("mov.b64 %0, {%1, %2};" : "=l"(r) : "f"(a), "f"(b)); return r;
}
__device__ __forceinline__ void upk2(ull v, float& a, float& b) {
    asm("mov.b64 {%0, %1}, %2;" : "=f"(a), "=f"(b) : "l"(v));
}
__device__ __forceinline__ ull fma2(ull a, ull b, ull c) {
    ull r; asm("fma.rn.f32x2 %0, %1, %2, %3;" : "=l"(r) : "l"(a), "l"(b), "l"(c));
    return r;
}
__device__ __forceinline__ ull add2(ull a, ull b) {
    ull r; asm("add.rn.f32x2 %0, %1, %2;" : "=l"(r) : "l"(a), "l"(b));
    return r;
}
__device__ __forceinline__ uint32_t f2tf32(float f) {
    uint32_t r; asm("cvt.rna.tf32.f32 %0, %1;" : "=r"(r) : "f"(f)); return r;
}
__device__ __forceinline__ void mma_tf32(float* c, const uint32_t* a, const uint32_t* b) {
    asm volatile(
        "mma.sync.aligned.m16n8k8.row.col.f32.tf32.tf32.f32 "
        "{%0,%1,%2,%3}, {%4,%5,%6,%7}, {%8,%9}, {%0,%1,%2,%3};"
        : "+f"(c[0]), "+f"(c[1]), "+f"(c[2]), "+f"(c[3])
        : "r"(a[0]), "r"(a[1]), "r"(a[2]), "r"(a[3]), "r"(b[0]), "r"(b[1]));
}

// ============================================================================
// Fused kernel: per (b, h) — conv(HMMA) + BN + axial attention.
// smem (floats):
//  q     [8][128]    @ 0      } Ws[32][132] (4224) aliases 0..4224 during conv
//  k     [8][128]    @ 1024   } psum[16][128] aliases q+k after phase 1
//  vdup  [128][16]u  @ 2048   (ull pairs v[i][j] duplicated, j-major)
//  relqk [16][256]   @ 6144   (q_emb/k_emb; relv after phase 1)
//  attnT [128][132]  @ 10240  (xs[128][132] aliases during conv)
//  invs  [128]       @ 27136
// total 27264 floats = 109056 B -> 2 CTAs/SM
// ============================================================================
#define AT_STRIDE 132
#define SM_Q     0
#define SM_K     1024
#define SM_VDUP  2048
#define SM_REL   6144
#define SM_ATT   10240
#define SM_INV   27136
#define SM_TOTAL 27264

__global__ void __launch_bounds__(256, 2)
fused_attn_kernel(const float* __restrict__ x, const float* __restrict__ W,
                  const float* __restrict__ gamma, const float* __restrict__ beta,
                  const float* __restrict__ mean, const float* __restrict__ var,
                  const float* __restrict__ relative, float* __restrict__ out)
{
    extern __shared__ float sm[];
    float* q     = sm + SM_Q;
    float* k     = sm + SM_K;
    ull*   vdup  = reinterpret_cast<ull*>(sm + SM_VDUP);
    float* relqk = sm + SM_REL;
    float* attnT = sm + SM_ATT;
    float* invs  = sm + SM_INV;
    float* psum  = sm + SM_Q;      // alias q/k after phase 1
    float* relv  = relqk;          // alias after phase 1
    float* Ws    = sm + SM_Q;      // alias q/k/vdup-head during conv
    float* xs    = sm + SM_ATT;    // alias attnT during conv

    const int t    = threadIdx.x;
    const int bid  = blockIdx.x;
    const int b    = bid >> 3;
    const int h    = bid & 7;
    const int warp = t >> 5, lane = t & 31;
    const int gp   = lane >> 2, tid4 = lane & 3;

    // ================= phase C0: stage W rows (this head) + x tile =============
#pragma unroll
    for (int it = 0; it < 4; ++it) {
        int e  = t + 256 * it;           // 0..1023
        int r  = e >> 5;
        int c4 = (e & 31) * 4;
        float4 wv = *reinterpret_cast<const float4*>(W + (r * 8 + h) * 128 + c4);
        float4 s;
        s.x = __uint_as_float(f2tf32(wv.x));
        s.y = __uint_as_float(f2tf32(wv.y));
        s.z = __uint_as_float(f2tf32(wv.z));
        s.w = __uint_as_float(f2tf32(wv.w));
        *reinterpret_cast<float4*>(Ws + r * AT_STRIDE + c4) = s;
    }
#pragma unroll
    for (int it = 0; it < 16; ++it) {
        int e  = t + 256 * it;           // 0..4095
        int c  = e >> 5;
        int d4 = (e & 31) * 4;
        float4 xv = *reinterpret_cast<const float4*>(x + (size_t)b * 16384 + c * 128 + d4);
        float4 s;
        s.x = __uint_as_float(f2tf32(xv.x));
        s.y = __uint_as_float(f2tf32(xv.y));
        s.z = __uint_as_float(f2tf32(xv.z));
        s.w = __uint_as_float(f2tf32(xv.w));
        *reinterpret_cast<float4*>(xs + c * AT_STRIDE + d4) = s;
    }
    __syncthreads();

    // ================= phase C1: conv MMA (M=32 r, N=128 d, K=128 c) ===========
    {
        const int wm = warp & 1, wn = warp >> 1;
        const int m0 = wm * 16, n0 = wn * 32;

        float acc[4][4];
#pragma unroll
        for (int i = 0; i < 4; ++i)
#pragma unroll
            for (int p = 0; p < 4; ++p) acc[i][p] = 0.f;

#pragma unroll
        for (int s = 0; s < 16; ++s) {
            uint32_t a[4];
            const float* abase = Ws + s * 8 + tid4;
            a[0] = __float_as_uint(abase[(m0 + gp) * AT_STRIDE]);
            a[1] = __float_as_uint(abase[(m0 + gp + 8) * AT_STRIDE]);
            a[2] = __float_as_uint(abase[(m0 + gp) * AT_STRIDE + 4]);
            a[3] = __float_as_uint(abase[(m0 + gp + 8) * AT_STRIDE + 4]);
            uint32_t bf[4][2];
            const float* bbase = xs + (s * 8 + tid4) * AT_STRIDE + n0 + gp;
#pragma unroll
            for (int nt = 0; nt < 4; ++nt) {
                bf[nt][0] = __float_as_uint(bbase[nt * 8]);
                bf[nt][1] = __float_as_uint(bbase[4 * AT_STRIDE + nt * 8]);
            }
#pragma unroll
            for (int nt = 0; nt < 4; ++nt)
                mma_tf32(acc[nt], a, bf[nt]);
        }
        __syncthreads();   // all Ws/xs reads done; q/k/vdup writable

        // epilogue: BN + route rows 0..7->q, 8..15->k, 16..31->vdup
        const int lr0 = m0 + gp, lr1 = lr0 + 8;     // lr0 in {0..7,16..23}, lr1 = lr0+8
        const int o0 = lr0 * 8 + h, o1 = lr1 * 8 + h;
        float iv0   = gamma[o0] * rsqrtf(var[o0] + EPS);
        float bias0 = beta[o0] - mean[o0] * iv0;
        float iv1   = gamma[o1] * rsqrtf(var[o1] + EPS);
        float bias1 = beta[o1] - mean[o1] * iv1;
        if (lr0 < 8) { iv0 *= QSCALE; bias0 *= QSCALE; }

#pragma unroll
        for (int nt = 0; nt < 4; ++nt) {
            const int d = n0 + nt * 8 + 2 * tid4;
            float y00 = acc[nt][0] * iv0 + bias0;   // (lr0, d)
            float y01 = acc[nt][1] * iv0 + bias0;   // (lr0, d+1)
            float y10 = acc[nt][2] * iv1 + bias1;   // (lr1, d)
            float y11 = acc[nt][3] * iv1 + bias1;   // (lr1, d+1)
            // route lr0
            if (lr0 < 8) {
                float2 s0; s0.x = y00; s0.y = y01;
                *reinterpret_cast<float2*>(q + lr0 * 128 + d) = s0;
            } else {                                  // lr0 in 16..23 -> v rows 0..7
                vdup[d * 16 + (lr0 - 16)]       = pk2(y00, y00);
                vdup[(d + 1) * 16 + (lr0 - 16)] = pk2(y01, y01);
            }
            // route lr1
            if (lr1 < 16) {                           // lr1 in 8..15 -> k rows 0..7
                float2 s1; s1.x = y10; s1.y = y11;
                *reinterpret_cast<float2*>(k + (lr1 - 8) * 128 + d) = s1;
            } else {                                  // lr1 in 24..31 -> v rows 8..15
                vdup[d * 16 + (lr1 - 16)]       = pk2(y10, y10);
                vdup[(d + 1) * 16 + (lr1 - 16)] = pk2(y11, y11);
            }
        }
        // load relqk (q_emb + k_emb)
        for (int idx = t; idx < 16 * 255; idx += 256) {
            int c = idx / 255, m = idx - c * 255;
            relqk[c * 256 + m] = relative[idx];
        }
    }
    __syncthreads();   // q/k/vdup/relqk ready; xs (attnT) dead

    // ================= phase 1: logits (dots + qr + kr) + exp ==================
    float sums[8];
    {
        const int tx = t & 15, ty = t >> 4;
        const int d0 = tx * 8, j0 = ty * 8;
        const int base = d0 - j0 + 120;

        ull acc[8][4];
#pragma unroll
        for (int a = 0; a < 8; ++a)
#pragma unroll
            for (int p = 0; p < 4; ++p) acc[a][p] = 0ULL;

#pragma unroll 2
        for (int i = 0; i < 8; ++i) {
            const float* qi = q + i * 128;
            const float* ki = k + i * 128;
            ull qp[4], kp[4];
            {
                ulonglong2 a0 = *reinterpret_cast<const ulonglong2*>(qi + d0);
                ulonglong2 a1 = *reinterpret_cast<const ulonglong2*>(qi + d0 + 4);
                qp[0] = a0.x; qp[1] = a0.y; qp[2] = a1.x; qp[3] = a1.y;
                ulonglong2 b0 = *reinterpret_cast<const ulonglong2*>(ki + d0);
                ulonglong2 b1 = *reinterpret_cast<const ulonglong2*>(ki + d0 + 4);
                kp[0] = b0.x; kp[1] = b0.y; kp[2] = b1.x; kp[3] = b1.y;
            }
            {
                float kj[8];
                *reinterpret_cast<float4*>(kj)     = *reinterpret_cast<const float4*>(ki + j0);
                *reinterpret_cast<float4*>(kj + 4) = *reinterpret_cast<const float4*>(ki + j0 + 4);
#pragma unroll
                for (int jj = 0; jj < 8; ++jj) {
                    ull kk2 = pk2(kj[jj], kj[jj]);
#pragma unroll
                    for (int p = 0; p < 4; ++p)
                        acc[jj][p] = fma2(qp[p], kk2, acc[jj][p]);
                }
            }
            {
                float wv[16];
                const float* rr = relqk + i * 256 + base;
#pragma unroll
                for (int u = 0; u < 4; ++u)
                    *reinterpret_cast<float4*>(wv + 4 * u) = *reinterpret_cast<const float4*>(rr + 4 * u);
                ull wo[7];
#pragma unroll
                for (int u = 0; u < 7; ++u) wo[u] = pk2(wv[2 * u + 1], wv[2 * u + 2]);
#pragma unroll
                for (int jj = 0; jj < 8; ++jj)
#pragma unroll
                    for (int p = 0; p < 4; ++p) {
                        const int a = 2 * p + 7 - jj;
                        ull pair = (a & 1) ? wo[a >> 1]
                                           : *reinterpret_cast<const ull*>(wv + a);
                        acc[jj][p] = fma2(qp[p], pair, acc[jj][p]);
                    }
            }
            {
                float wv[16];
                const float* rr = relqk + (8 + i) * 256 + base;
#pragma unroll
                for (int u = 0; u < 4; ++u)
                    *reinterpret_cast<float4*>(wv + 4 * u) = *reinterpret_cast<const float4*>(rr + 4 * u);
                ull wo[7];
#pragma unroll
                for (int u = 0; u < 7; ++u) wo[u] = pk2(wv[2 * u + 1], wv[2 * u + 2]);
#pragma unroll
                for (int jj = 0; jj < 8; ++jj)
#pragma unroll
                    for (int p = 0; p < 4; ++p) {
                        const int a = 2 * p + 7 - jj;
                        ull pair = (a & 1) ? wo[a >> 1]
                                           : *reinterpret_cast<const ull*>(wv + a);
                        acc[jj][p] = fma2(kp[p], pair, acc[jj][p]);
                    }
            }
        }

#pragma unroll
        for (int dd = 0; dd < 8; ++dd) sums[dd] = 0.f;
#pragma unroll
        for (int jj = 0; jj < 8; ++jj) {
            float* dst = attnT + (j0 + jj) * AT_STRIDE + d0;
#pragma unroll
            for (int p = 0; p < 4; ++p) {
                float lo, hi;
                upk2(acc[jj][p], lo, hi);
                float e0 = __expf(lo), e1 = __expf(hi);
                sums[2 * p]     += e0;
                sums[2 * p + 1] += e1;
                float2 s; s.x = e0; s.y = e1;
                *reinterpret_cast<float2*>(dst + 2 * p) = s;
            }
        }
    }
    __syncthreads();

    // ================= phase 2: psum + relv + invs ==============================
    {
        const int tx = t & 15, ty = t >> 4;
        const int d0 = tx * 8;
#pragma unroll
        for (int dd = 0; dd < 8; ++dd)
            psum[ty * 128 + d0 + dd] = sums[dd];
        for (int idx = t; idx < 16 * 255; idx += 256) {
            int c = idx / 255, m = idx - c * 255;
            relv[c * 256 + m] = relative[16 * 255 + idx];
        }
    }
    __syncthreads();
    if (t < 128) {
        float s = 0.f;
#pragma unroll
        for (int ty2 = 0; ty2 < 16; ++ty2) s += psum[ty2 * 128 + t];
        invs[t] = 1.0f / s;
    }
    __syncthreads();

    // ================= phase 3: out + kv =========================================
    {
        const int i0  = (warp & 3) * 4;
        const int jh  = warp >> 2;
        const int d0  = lane * 4;
        const int jb0 = jh * 64;

        ull acc[4][2];
#pragma unroll
        for (int ii = 0; ii < 4; ++ii) { acc[ii][0] = 0ULL; acc[ii][1] = 0ULL; }

        ull we[4][3], wo[4][3];
        float lastf0[4];
#pragma unroll
        for (int ii = 0; ii < 4; ++ii) {
            const float* rp = relv + (i0 + ii) * 256 + (d0 - jb0 + 124);
            float4 lo4 = *reinterpret_cast<const float4*>(rp);
            float4 hi4 = *reinterpret_cast<const float4*>(rp + 4);
            we[ii][0] = pk2(lo4.x, lo4.y);
            we[ii][1] = pk2(lo4.z, lo4.w);
            we[ii][2] = pk2(hi4.x, hi4.y);
            wo[ii][0] = pk2(lo4.y, lo4.z);
            wo[ii][1] = pk2(lo4.w, hi4.x);
            wo[ii][2] = pk2(hi4.y, hi4.z);
            lastf0[ii] = lo4.x;
        }

        for (int g = 0; g < 16; ++g) {
            const int jb = jb0 + g * 4;
            if (g > 0) {
                const int baseg = d0 - jb + 124;
#pragma unroll
                for (int ii = 0; ii < 4; ++ii) {
                    we[ii][2] = we[ii][0];
                    wo[ii][2] = wo[ii][0];
                    float4 f = *reinterpret_cast<const float4*>(relv + (i0 + ii) * 256 + baseg);
                    we[ii][0] = pk2(f.x, f.y);
                    we[ii][1] = pk2(f.z, f.w);
                    wo[ii][0] = pk2(f.y, f.z);
                    wo[ii][1] = pk2(f.w, lastf0[ii]);
                    lastf0[ii] = f.x;
                }
            }
#pragma unroll
            for (int jj = 0; jj < 4; ++jj) {
                const int j = jb + jj;
                ulonglong2 at2 = *reinterpret_cast<const ulonglong2*>(attnT + j * AT_STRIDE + d0);
                const ull* vr = vdup + j * 16 + i0;
                ulonglong2 va = *reinterpret_cast<const ulonglong2*>(vr);
                ulonglong2 vb = *reinterpret_cast<const ulonglong2*>(vr + 2);
                ull vp[4]; vp[0] = va.x; vp[1] = va.y; vp[2] = vb.x; vp[3] = vb.y;
#pragma unroll
                for (int ii = 0; ii < 4; ++ii) {
                    acc[ii][0] = fma2(at2.x, vp[ii], acc[ii][0]);
                    acc[ii][1] = fma2(at2.y, vp[ii], acc[ii][1]);
                    const int o0 = 3 - jj;
                    const int o1 = 5 - jj;
                    ull pr0 = (o0 & 1) ? wo[ii][o0 >> 1] : we[ii][o0 >> 1];
                    ull pr1 = (o1 & 1) ? wo[ii][o1 >> 1] : we[ii][o1 >> 1];
                    acc[ii][0] = fma2(at2.x, pr0, acc[ii][0]);
                    acc[ii][1] = fma2(at2.y, pr1, acc[ii][1]);
                }
            }
        }

        __syncthreads();
        ull* red = reinterpret_cast<ull*>(attnT);

        if (jh == 1) {
#pragma unroll
            for (int ii = 0; ii < 4; ++ii) {
                red[(i0 + ii) * 64 + lane * 2 + 0] = acc[ii][0];
                red[(i0 + ii) * 64 + lane * 2 + 1] = acc[ii][1];
            }
        }
        __syncthreads();

        if (jh == 0) {
            float4 iv4 = *reinterpret_cast<const float4*>(invs + d0);
            float* ob = out + (size_t)b * 16384 + h * 2048;
#pragma unroll
            for (int ii = 0; ii < 4; ++ii) {
                ull s0 = add2(acc[ii][0], red[(i0 + ii) * 64 + lane * 2 + 0]);
                ull s1 = add2(acc[ii][1], red[(i0 + ii) * 64 + lane * 2 + 1]);
                float4 r;
                upk2(s0, r.x, r.y);
                upk2(s1, r.z, r.w);
                r.x *= iv4.x; r.y *= iv4.y; r.z *= iv4.z; r.w *= iv4.w;
                *reinterpret_cast<float4*>(ob + (i0 + ii) * 128 + d0) = r;
            }
        }
    }
}

// ============================================================================
extern "C" void kernel_launch(void* const* d_in, const int* in_sizes, int n_in,
                              void* d_out, int out_size) {
    const float* x        = (const float*)d_in[0];
    const float* W        = (const float*)d_in[1];
    const float* gamma    = (const float*)d_in[2];
    const float* beta     = (const float*)d_in[3];
    const float* mean     = (const float*)d_in[4];
    const float* var      = (const float*)d_in[5];
    const float* relative = (const float*)d_in[6];
    float* out = (float*)d_out;

    int nb = in_sizes[0] / (INC * DIM);

    const int smemB = SM_TOTAL * (int)sizeof(float);   // 109056
    cudaFuncSetAttribute(fused_attn_kernel, cudaFuncAttributeMaxDynamicSharedMemorySize, smemB);

    fused_attn_kernel<<<nb * HEADS, 256, smemB>>>(x, W, gamma, beta, mean, var,
                                                  relative, out);
}

// round 11
// speedup vs baseline: 1.1730x; 1.1063x over previous
#include <cuda_runtime.h>
#include <cuda_fp16.h>
#include <math.h>
#include <stdint.h>

#define HEADS 8
#define DIM 128
#define INC 128
#define EPS 1e-5f
#define QSCALE 0.08838834764831845f   // 128^-0.5

typedef unsigned long long ull;

__device__ float g_qkv[2048 * 32768];   // [b][h][r(0..31)][d]

__device__ __forceinline__ ull pk2(float a, float b) {
    ull r; asm("mov.b64 %0, {%1, %2};" : "=l"(r) : "f"(a), "f"(b)); return r;
}
__device__ __forceinline__ void upk2(ull v, float& a, float& b) {
    asm("mov.b64 {%0, %1}, %2;" : "=f"(a), "=f"(b) : "l"(v));
}
__device__ __forceinline__ ull fma2(ull a, ull b, ull c) {
    ull r; asm("fma.rn.f32x2 %0, %1, %2, %3;" : "=l"(r) : "l"(a), "l"(b), "l"(c));
    return r;
}
__device__ __forceinline__ ull add2(ull a, ull b) {
    ull r; asm("add.rn.f32x2 %0, %1, %2;" : "=l"(r) : "l"(a), "l"(b));
    return r;
}
__device__ __forceinline__ uint32_t f2tf32(float f) {
    uint32_t r; asm("cvt.rna.tf32.f32 %0, %1;" : "=r"(r) : "f"(f)); return r;
}
__device__ __forceinline__ void mma_tf32(float* c, const uint32_t* a, const uint32_t* b) {
    asm volatile(
        "mma.sync.aligned.m16n8k8.row.col.f32.tf32.tf32.f32 "
        "{%0,%1,%2,%3}, {%4,%5,%6,%7}, {%8,%9}, {%0,%1,%2,%3};"
        : "+f"(c[0]), "+f"(c[1]), "+f"(c[2]), "+f"(c[3])
        : "r"(a[0]), "r"(a[1]), "r"(a[2]), "r"(a[3]), "r"(b[0]), "r"(b[1]));
}

// ============================================================================
// Kernel A: conv1x1 + BN via mma.sync tf32 (round-7 verified, 155 us)
// ============================================================================
#define CA_STR 132
#define CB_STR 136
#define CV_BS  (128 * CA_STR)
#define CV_IV  (CV_BS + 128 * CB_STR)
#define CV_BB  (CV_IV + 128)
#define CV_TOT (CV_BB + 128)

__global__ void __launch_bounds__(512, 1)
conv_bn_mma_kernel(const float* __restrict__ x, const float* __restrict__ W,
                   const float* __restrict__ gamma, const float* __restrict__ beta,
                   const float* __restrict__ mean, const float* __restrict__ var,
                   float* __restrict__ qkv)
{
    extern __shared__ float sm[];
    float* As  = sm;
    float* Bs  = sm + CV_BS;
    float* ivs = sm + CV_IV;
    float* bss = sm + CV_BB;

    const int t      = threadIdx.x;
    const int b      = blockIdx.x >> 1;
    const int o_base = (blockIdx.x & 1) * 128;

#pragma unroll
    for (int it = 0; it < 8; ++it) {
        int e  = t + 512 * it;
        int o  = e >> 5;
        int c4 = (e & 31) * 4;
        float4 wv = *reinterpret_cast<const float4*>(W + (o_base + o) * 128 + c4);
        float4 s;
        s.x = __uint_as_float(f2tf32(wv.x));
        s.y = __uint_as_float(f2tf32(wv.y));
        s.z = __uint_as_float(f2tf32(wv.z));
        s.w = __uint_as_float(f2tf32(wv.w));
        *reinterpret_cast<float4*>(As + o * CA_STR + c4) = s;
    }
#pragma unroll
    for (int it = 0; it < 8; ++it) {
        int e  = t + 512 * it;
        int c  = e >> 5;
        int d4 = (e & 31) * 4;
        float4 xv = *reinterpret_cast<const float4*>(x + (size_t)b * 16384 + c * 128 + d4);
        float4 s;
        s.x = __uint_as_float(f2tf32(xv.x));
        s.y = __uint_as_float(f2tf32(xv.y));
        s.z = __uint_as_float(f2tf32(xv.z));
        s.w = __uint_as_float(f2tf32(xv.w));
        *reinterpret_cast<float4*>(Bs + c * CB_STR + d4) = s;
    }
    if (t < 128) {
        int o = o_base + t;
        float iv   = gamma[o] * rsqrtf(var[o] + EPS);
        float bias = beta[o] - mean[o] * iv;
        if (o < 64) { iv *= QSCALE; bias *= QSCALE; }
        ivs[t] = iv;
        bss[t] = bias;
    }
    __syncthreads();

    const int warp = t >> 5, lane = t & 31;
    const int wm = warp & 3, wn = warp >> 2;        // 16 warps: 4 x 4
    const int m0 = wm * 32, n0 = wn * 32;
    const int gp = lane >> 2, tid4 = lane & 3;

    float acc[8][4];
#pragma unroll
    for (int i = 0; i < 8; ++i)
#pragma unroll
        for (int p = 0; p < 4; ++p) acc[i][p] = 0.f;

#pragma unroll
    for (int s = 0; s < 16; ++s) {
        uint32_t a[2][4];
        const float* abase = As + s * 8 + tid4;
#pragma unroll
        for (int mt = 0; mt < 2; ++mt) {
            int r0 = m0 + mt * 16 + gp;
            a[mt][0] = __float_as_uint(abase[r0 * CA_STR]);
            a[mt][1] = __float_as_uint(abase[(r0 + 8) * CA_STR]);
            a[mt][2] = __float_as_uint(abase[r0 * CA_STR + 4]);
            a[mt][3] = __float_as_uint(abase[(r0 + 8) * CA_STR + 4]);
        }
        uint32_t bf[4][2];
        const float* bbase = Bs + (s * 8 + tid4) * CB_STR + n0 + gp;
#pragma unroll
        for (int nt = 0; nt < 4; ++nt) {
            bf[nt][0] = __float_as_uint(bbase[nt * 8]);
            bf[nt][1] = __float_as_uint(bbase[4 * CB_STR + nt * 8]);
        }
#pragma unroll
        for (int mt = 0; mt < 2; ++mt)
#pragma unroll
            for (int nt = 0; nt < 4; ++nt)
                mma_tf32(acc[mt * 4 + nt], a[mt], bf[nt]);
    }

#pragma unroll
    for (int mt = 0; mt < 2; ++mt) {
        int lr0 = m0 + mt * 16 + gp;
        int lr1 = lr0 + 8;
        float iv0 = ivs[lr0], bv0 = bss[lr0];
        float iv1 = ivs[lr1], bv1 = bss[lr1];
        int o0 = o_base + lr0, o1 = o_base + lr1;
        float* d00 = qkv + (size_t)b * 32768 + (o0 & 7) * 4096 + (o0 >> 3) * 128;
        float* d01 = qkv + (size_t)b * 32768 + (o1 & 7) * 4096 + (o1 >> 3) * 128;
#pragma unroll
        for (int nt = 0; nt < 4; ++nt) {
            int d = n0 + nt * 8 + 2 * tid4;
            const float* a4 = acc[mt * 4 + nt];
            float2 s0, s1;
            s0.x = a4[0] * iv0 + bv0; s0.y = a4[1] * iv0 + bv0;
            s1.x = a4[2] * iv1 + bv1; s1.y = a4[3] * iv1 + bv1;
            *reinterpret_cast<float2*>(d00 + d) = s0;
            *reinterpret_cast<float2*>(d01 + d) = s1;
        }
    }
}

// ============================================================================
// Kernel B: attention per (b, h) — fp16 attnT + per-column max
// smem (floats):
//  q      [8][128]    @ 0      (pmax/psum [16][128] alias q+k after logits)
//  k      [8][128]    @ 1024
//  vdup   [128][16]u  @ 2048
//  relqk  [16][256]   @ 6144   (relv alias)
//  attnTh half[128][136] @ 10240 (8704 floats; red alias after reads)
//  cmax/invs [128]    @ 18944
// total 19072 floats = 76288 B -> 2 CTAs/SM (reg-capped)
// ============================================================================
#define ATH_STR  136
#define SM_Q     0
#define SM_K     1024
#define SM_VDUP  2048
#define SM_REL   6144
#define SM_ATTH  10240
#define SM_CMAX  18944
#define SM_TOTAL 19072

__global__ void __launch_bounds__(256, 2)
attn_kernel(const float* __restrict__ qkv, const float* __restrict__ relative,
            float* __restrict__ out)
{
    extern __shared__ float sm[];
    float*  q     = sm + SM_Q;
    float*  k     = sm + SM_K;
    ull*    vdup  = reinterpret_cast<ull*>(sm + SM_VDUP);
    float*  relqk = sm + SM_REL;
    __half* atth  = reinterpret_cast<__half*>(sm + SM_ATTH);
    float*  cmax  = sm + SM_CMAX;   // colmax, later invs
    float*  psum  = sm + SM_Q;      // pmax then psum, aliases q/k
    float*  relv  = relqk;

    const int t   = threadIdx.x;
    const int bid = blockIdx.x;
    const int b   = bid >> 3;
    const int h   = bid & 7;

    // ---------------- phase 0: load q/k/vdup + relqk --------------------------
    {
        const float* src = qkv + (size_t)b * 32768 + h * 4096;
#pragma unroll
        for (int it = 0; it < 4; ++it) {
            int e4 = t + 256 * it;
            int r  = e4 >> 5;
            int dw = (e4 & 31) * 4;
            float4 val = *reinterpret_cast<const float4*>(src + r * 128 + dw);
            if (r < 8) {
                *reinterpret_cast<float4*>(q + r * 128 + dw) = val;
            } else if (r < 16) {
                *reinterpret_cast<float4*>(k + (r - 8) * 128 + dw) = val;
            } else {
                int i = r - 16;
                vdup[(dw + 0) * 16 + i] = pk2(val.x, val.x);
                vdup[(dw + 1) * 16 + i] = pk2(val.y, val.y);
                vdup[(dw + 2) * 16 + i] = pk2(val.z, val.z);
                vdup[(dw + 3) * 16 + i] = pk2(val.w, val.w);
            }
        }
        for (int idx = t; idx < 16 * 255; idx += 256) {
            int c = idx / 255, m = idx - c * 255;
            relqk[c * 256 + m] = relative[idx];
        }
    }
    __syncthreads();

    // ---------------- phase 1: logits (dots + qr + kr) ------------------------
    const int tx = t & 15, ty = t >> 4;
    const int d0l = tx * 8, j0l = ty * 8;
    ull acc[8][4];
    {
        const int base = d0l - j0l + 120;
#pragma unroll
        for (int a = 0; a < 8; ++a)
#pragma unroll
            for (int p = 0; p < 4; ++p) acc[a][p] = 0ULL;

#pragma unroll 2
        for (int i = 0; i < 8; ++i) {
            const float* qi = q + i * 128;
            const float* ki = k + i * 128;
            ull qp[4], kp[4];
            {
                ulonglong2 a0 = *reinterpret_cast<const ulonglong2*>(qi + d0l);
                ulonglong2 a1 = *reinterpret_cast<const ulonglong2*>(qi + d0l + 4);
                qp[0] = a0.x; qp[1] = a0.y; qp[2] = a1.x; qp[3] = a1.y;
                ulonglong2 b0 = *reinterpret_cast<const ulonglong2*>(ki + d0l);
                ulonglong2 b1 = *reinterpret_cast<const ulonglong2*>(ki + d0l + 4);
                kp[0] = b0.x; kp[1] = b0.y; kp[2] = b1.x; kp[3] = b1.y;
            }
            {
                float kj[8];
                *reinterpret_cast<float4*>(kj)     = *reinterpret_cast<const float4*>(ki + j0l);
                *reinterpret_cast<float4*>(kj + 4) = *reinterpret_cast<const float4*>(ki + j0l + 4);
#pragma unroll
                for (int jj = 0; jj < 8; ++jj) {
                    ull kk2 = pk2(kj[jj], kj[jj]);
#pragma unroll
                    for (int p = 0; p < 4; ++p)
                        acc[jj][p] = fma2(qp[p], kk2, acc[jj][p]);
                }
            }
            {
                float wv[16];
                const float* rr = relqk + i * 256 + base;
#pragma unroll
                for (int u = 0; u < 4; ++u)
                    *reinterpret_cast<float4*>(wv + 4 * u) = *reinterpret_cast<const float4*>(rr + 4 * u);
                ull wo[7];
#pragma unroll
                for (int u = 0; u < 7; ++u) wo[u] = pk2(wv[2 * u + 1], wv[2 * u + 2]);
#pragma unroll
                for (int jj = 0; jj < 8; ++jj)
#pragma unroll
                    for (int p = 0; p < 4; ++p) {
                        const int a = 2 * p + 7 - jj;
                        ull pair = (a & 1) ? wo[a >> 1]
                                           : *reinterpret_cast<const ull*>(wv + a);
                        acc[jj][p] = fma2(qp[p], pair, acc[jj][p]);
                    }
            }
            {
                float wv[16];
                const float* rr = relqk + (8 + i) * 256 + base;
#pragma unroll
                for (int u = 0; u < 4; ++u)
                    *reinterpret_cast<float4*>(wv + 4 * u) = *reinterpret_cast<const float4*>(rr + 4 * u);
                ull wo[7];
#pragma unroll
                for (int u = 0; u < 7; ++u) wo[u] = pk2(wv[2 * u + 1], wv[2 * u + 2]);
#pragma unroll
                for (int jj = 0; jj < 8; ++jj)
#pragma unroll
                    for (int p = 0; p < 4; ++p) {
                        const int a = 2 * p + 7 - jj;
                        ull pair = (a & 1) ? wo[a >> 1]
                                           : *reinterpret_cast<const ull*>(wv + a);
                        acc[jj][p] = fma2(kp[p], pair, acc[jj][p]);
                    }
            }
        }
    }

    // ---------------- phase 1b: column max ladder ------------------------------
    {
        float tmax[8];
#pragma unroll
        for (int dd = 0; dd < 8; ++dd) tmax[dd] = -1e30f;
#pragma unroll
        for (int jj = 0; jj < 8; ++jj)
#pragma unroll
            for (int p = 0; p < 4; ++p) {
                float lo, hi;
                upk2(acc[jj][p], lo, hi);
                tmax[2 * p]     = fmaxf(tmax[2 * p], lo);
                tmax[2 * p + 1] = fmaxf(tmax[2 * p + 1], hi);
            }
        __syncthreads();   // q/k reads done everywhere; pmax may overwrite
        float4* pm = reinterpret_cast<float4*>(psum + ty * 128 + d0l);
        pm[0] = make_float4(tmax[0], tmax[1], tmax[2], tmax[3]);
        pm[1] = make_float4(tmax[4], tmax[5], tmax[6], tmax[7]);
    }
    __syncthreads();
    if (t < 128) {
        float m = -1e30f;
#pragma unroll
        for (int r = 0; r < 16; ++r) m = fmaxf(m, psum[r * 128 + t]);
        cmax[t] = m;
    }
    __syncthreads();

    // ---------------- phase 1c: exp + fp16 store + sums; relv load -------------
    {
        float cm[8];
        *reinterpret_cast<float4*>(cm)     = *reinterpret_cast<const float4*>(cmax + d0l);
        *reinterpret_cast<float4*>(cm + 4) = *reinterpret_cast<const float4*>(cmax + d0l + 4);
        float sums[8];
#pragma unroll
        for (int dd = 0; dd < 8; ++dd) sums[dd] = 0.f;
#pragma unroll
        for (int jj = 0; jj < 8; ++jj) {
            __half2 hh[4];
#pragma unroll
            for (int p = 0; p < 4; ++p) {
                float lo, hi;
                upk2(acc[jj][p], lo, hi);
                float e0 = __expf(lo - cm[2 * p]);
                float e1 = __expf(hi - cm[2 * p + 1]);
                sums[2 * p]     += e0;
                sums[2 * p + 1] += e1;
                hh[p] = __floats2half2_rn(e0, e1);
            }
            *reinterpret_cast<uint4*>(atth + (j0l + jj) * ATH_STR + d0l) =
                *reinterpret_cast<uint4*>(hh);
        }
        // psum (overwrites pmax — colmax already extracted)
        float4* ps = reinterpret_cast<float4*>(psum + ty * 128 + d0l);
        ps[0] = make_float4(sums[0], sums[1], sums[2], sums[3]);
        ps[1] = make_float4(sums[4], sums[5], sums[6], sums[7]);
        // relv load (relqk dead)
        for (int idx = t; idx < 16 * 255; idx += 256) {
            int c = idx / 255, m = idx - c * 255;
            relv[c * 256 + m] = relative[16 * 255 + idx];
        }
    }
    __syncthreads();
    if (t < 128) {
        float s = 0.f;
#pragma unroll
        for (int r = 0; r < 16; ++r) s += psum[r * 128 + t];
        cmax[t] = 1.0f / s;      // cmax now holds invs
    }
    __syncthreads();

    // ---------------- phase 3: out + kv ----------------------------------------
    {
        const int lane = t & 31;
        const int wd   = t >> 5;
        const int i0   = (wd & 3) * 4;
        const int jh   = wd >> 2;
        const int d0   = lane * 4;
        const int jb0  = jh * 64;

        ull acco[4][2];
#pragma unroll
        for (int ii = 0; ii < 4; ++ii) { acco[ii][0] = 0ULL; acco[ii][1] = 0ULL; }

        ull we[4][3], wo[4][3];
        float lastf0[4];
#pragma unroll
        for (int ii = 0; ii < 4; ++ii) {
            const float* rp = relv + (i0 + ii) * 256 + (d0 - jb0 + 124);
            float4 lo4 = *reinterpret_cast<const float4*>(rp);
            float4 hi4 = *reinterpret_cast<const float4*>(rp + 4);
            we[ii][0] = pk2(lo4.x, lo4.y);
            we[ii][1] = pk2(lo4.z, lo4.w);
            we[ii][2] = pk2(hi4.x, hi4.y);
            wo[ii][0] = pk2(lo4.y, lo4.z);
            wo[ii][1] = pk2(lo4.w, hi4.x);
            wo[ii][2] = pk2(hi4.y, hi4.z);
            lastf0[ii] = lo4.x;
        }

        for (int g = 0; g < 16; ++g) {
            const int jb = jb0 + g * 4;
            if (g > 0) {
                const int baseg = d0 - jb + 124;
#pragma unroll
                for (int ii = 0; ii < 4; ++ii) {
                    we[ii][2] = we[ii][0];
                    wo[ii][2] = wo[ii][0];
                    float4 f = *reinterpret_cast<const float4*>(relv + (i0 + ii) * 256 + baseg);
                    we[ii][0] = pk2(f.x, f.y);
                    we[ii][1] = pk2(f.z, f.w);
                    wo[ii][0] = pk2(f.y, f.z);
                    wo[ii][1] = pk2(f.w, lastf0[ii]);
                    lastf0[ii] = f.x;
                }
            }
#pragma unroll
            for (int jj = 0; jj < 4; ++jj) {
                const int j = jb + jj;
                // fp16 attn read: 4 halves (8B) -> two f32 pairs
                uint2 uu = *reinterpret_cast<const uint2*>(atth + j * ATH_STR + d0);
                float2 f01 = __half22float2(*reinterpret_cast<__half2*>(&uu.x));
                float2 f23 = __half22float2(*reinterpret_cast<__half2*>(&uu.y));
                ull atx = pk2(f01.x, f01.y);
                ull aty = pk2(f23.x, f23.y);
                const ull* vr = vdup + j * 16 + i0;
                ulonglong2 va = *reinterpret_cast<const ulonglong2*>(vr);
                ulonglong2 vb = *reinterpret_cast<const ulonglong2*>(vr + 2);
                ull vp[4]; vp[0] = va.x; vp[1] = va.y; vp[2] = vb.x; vp[3] = vb.y;
#pragma unroll
                for (int ii = 0; ii < 4; ++ii) {
                    acco[ii][0] = fma2(atx, vp[ii], acco[ii][0]);
                    acco[ii][1] = fma2(aty, vp[ii], acco[ii][1]);
                    const int o0 = 3 - jj;
                    const int o1 = 5 - jj;
                    ull pr0 = (o0 & 1) ? wo[ii][o0 >> 1] : we[ii][o0 >> 1];
                    ull pr1 = (o1 & 1) ? wo[ii][o1 >> 1] : we[ii][o1 >> 1];
                    acco[ii][0] = fma2(atx, pr0, acco[ii][0]);
                    acco[ii][1] = fma2(aty, pr1, acco[ii][1]);
                }
            }
        }

        __syncthreads();           // all attn reads done
        ull* red = reinterpret_cast<ull*>(sm + SM_ATTH);

        if (jh == 1) {
#pragma unroll
            for (int ii = 0; ii < 4; ++ii) {
                red[(i0 + ii) * 64 + lane * 2 + 0] = acco[ii][0];
                red[(i0 + ii) * 64 + lane * 2 + 1] = acco[ii][1];
            }
        }
        __syncthreads();

        if (jh == 0) {
            float4 iv4 = *reinterpret_cast<const float4*>(cmax + d0);
            float* ob = out + (size_t)b * 16384 + h * 2048;
#pragma unroll
            for (int ii = 0; ii < 4; ++ii) {
                ull s0 = add2(acco[ii][0], red[(i0 + ii) * 64 + lane * 2 + 0]);
                ull s1 = add2(acco[ii][1], red[(i0 + ii) * 64 + lane * 2 + 1]);
                float4 r;
                upk2(s0, r.x, r.y);
                upk2(s1, r.z, r.w);
                r.x *= iv4.x; r.y *= iv4.y; r.z *= iv4.z; r.w *= iv4.w;
                *reinterpret_cast<float4*>(ob + (i0 + ii) * 128 + d0) = r;
            }
        }
    }
}

// ============================================================================
extern "C" void kernel_launch(void* const* d_in, const int* in_sizes, int n_in,
                              void* d_out, int out_size) {
    const float* x        = (const float*)d_in[0];
    const float* W        = (const float*)d_in[1];
    const float* gamma    = (const float*)d_in[2];
    const float* beta     = (const float*)d_in[3];
    const float* mean     = (const float*)d_in[4];
    const float* var      = (const float*)d_in[5];
    const float* relative = (const float*)d_in[6];
    float* out = (float*)d_out;

    int nb = in_sizes[0] / (INC * DIM);

    float* scratch;
    cudaGetSymbolAddress((void**)&scratch, g_qkv);

    const int smemA = CV_TOT * (int)sizeof(float);     // 138240
    const int smemB = SM_TOTAL * (int)sizeof(float);   // 76288
    cudaFuncSetAttribute(conv_bn_mma_kernel, cudaFuncAttributeMaxDynamicSharedMemorySize, smemA);
    cudaFuncSetAttribute(attn_kernel,        cudaFuncAttributeMaxDynamicSharedMemorySize, smemB);

    conv_bn_mma_kernel<<<nb * 2, 512, smemA>>>(x, W, gamma, beta, mean, var, scratch);
    attn_kernel<<<nb * HEADS, 256, smemB>>>(scratch, relative, out);
}

// round 13
// speedup vs baseline: 1.3417x; 1.1439x over previous
#include <cuda_runtime.h>
#include <cuda_fp16.h>
#include <math.h>
#include <stdint.h>

#define HEADS 8
#define DIM 128
#define INC 128
#define EPS 1e-5f
#define QSCALE 0.08838834764831845f   // 128^-0.5

typedef unsigned long long ull;

__device__ float g_qkv[2048 * 32768];   // [b][h][r(0..31)][d]

__device__ __forceinline__ ull pk2(float a, float b) {
    ull r; asm("mov.b64 %0, {%1, %2};" : "=l"(r) : "f"(a), "f"(b)); return r;
}
__device__ __forceinline__ void upk2(ull v, float& a, float& b) {
    asm("mov.b64 {%0, %1}, %2;" : "=f"(a), "=f"(b) : "l"(v));
}
__device__ __forceinline__ ull fma2(ull a, ull b, ull c) {
    ull r; asm("fma.rn.f32x2 %0, %1, %2, %3;" : "=l"(r) : "l"(a), "l"(b), "l"(c));
    return r;
}
__device__ __forceinline__ ull add2(ull a, ull b) {
    ull r; asm("add.rn.f32x2 %0, %1, %2;" : "=l"(r) : "l"(a), "l"(b));
    return r;
}
__device__ __forceinline__ uint32_t f2tf32(float f) {
    uint32_t r; asm("cvt.rna.tf32.f32 %0, %1;" : "=r"(r) : "f"(f)); return r;
}
__device__ __forceinline__ void mma_tf32(float* c, const uint32_t* a, const uint32_t* b) {
    asm volatile(
        "mma.sync.aligned.m16n8k8.row.col.f32.tf32.tf32.f32 "
        "{%0,%1,%2,%3}, {%4,%5,%6,%7}, {%8,%9}, {%0,%1,%2,%3};"
        : "+f"(c[0]), "+f"(c[1]), "+f"(c[2]), "+f"(c[3])
        : "r"(a[0]), "r"(a[1]), "r"(a[2]), "r"(a[3]), "r"(b[0]), "r"(b[1]));
}
__device__ __forceinline__ void mma_f16(float* c, const uint32_t* a, const uint32_t* b) {
    asm volatile(
        "mma.sync.aligned.m16n8k16.row.col.f32.f16.f16.f32 "
        "{%0,%1,%2,%3}, {%4,%5,%6,%7}, {%8,%9}, {%0,%1,%2,%3};"
        : "+f"(c[0]), "+f"(c[1]), "+f"(c[2]), "+f"(c[3])
        : "r"(a[0]), "r"(a[1]), "r"(a[2]), "r"(a[3]), "r"(b[0]), "r"(b[1]));
}
__device__ __forceinline__ void ldsm_x4_t(uint32_t& r0, uint32_t& r1,
                                          uint32_t& r2, uint32_t& r3, uint32_t addr) {
    asm volatile("ldmatrix.sync.aligned.m8n8.x4.trans.shared.b16 {%0,%1,%2,%3}, [%4];"
                 : "=r"(r0), "=r"(r1), "=r"(r2), "=r"(r3) : "r"(addr));
}
__device__ __forceinline__ void ldsm_x2(uint32_t& r0, uint32_t& r1, uint32_t addr) {
    asm volatile("ldmatrix.sync.aligned.m8n8.x2.shared.b16 {%0,%1}, [%2];"
                 : "=r"(r0), "=r"(r1) : "r"(addr));
}
__device__ __forceinline__ uint32_t smem_u32(const void* p) {
    uint32_t a;
    asm("{ .reg .u64 t; cvta.to.shared.u64 t, %1; cvt.u32.u64 %0, t; }"
        : "=r"(a) : "l"(p));
    return a;
}

// ============================================================================
// Kernel A: conv1x1 + BN via mma.sync tf32 (round-11 verified)
// ============================================================================
#define CA_STR 132
#define CB_STR 136
#define CV_BS  (128 * CA_STR)
#define CV_IV  (CV_BS + 128 * CB_STR)
#define CV_BB  (CV_IV + 128)
#define CV_TOT (CV_BB + 128)

__global__ void __launch_bounds__(512, 1)
conv_bn_mma_kernel(const float* __restrict__ x, const float* __restrict__ W,
                   const float* __restrict__ gamma, const float* __restrict__ beta,
                   const float* __restrict__ mean, const float* __restrict__ var,
                   float* __restrict__ qkv)
{
    extern __shared__ float sm[];
    float* As  = sm;
    float* Bs  = sm + CV_BS;
    float* ivs = sm + CV_IV;
    float* bss = sm + CV_BB;

    const int t      = threadIdx.x;
    const int b      = blockIdx.x >> 1;
    const int o_base = (blockIdx.x & 1) * 128;

#pragma unroll
    for (int it = 0; it < 8; ++it) {
        int e  = t + 512 * it;
        int o  = e >> 5;
        int c4 = (e & 31) * 4;
        float4 wv = *reinterpret_cast<const float4*>(W + (o_base + o) * 128 + c4);
        float4 s;
        s.x = __uint_as_float(f2tf32(wv.x));
        s.y = __uint_as_float(f2tf32(wv.y));
        s.z = __uint_as_float(f2tf32(wv.z));
        s.w = __uint_as_float(f2tf32(wv.w));
        *reinterpret_cast<float4*>(As + o * CA_STR + c4) = s;
    }
#pragma unroll
    for (int it = 0; it < 8; ++it) {
        int e  = t + 512 * it;
        int c  = e >> 5;
        int d4 = (e & 31) * 4;
        float4 xv = *reinterpret_cast<const float4*>(x + (size_t)b * 16384 + c * 128 + d4);
        float4 s;
        s.x = __uint_as_float(f2tf32(xv.x));
        s.y = __uint_as_float(f2tf32(xv.y));
        s.z = __uint_as_float(f2tf32(xv.z));
        s.w = __uint_as_float(f2tf32(xv.w));
        *reinterpret_cast<float4*>(Bs + c * CB_STR + d4) = s;
    }
    if (t < 128) {
        int o = o_base + t;
        float iv   = gamma[o] * rsqrtf(var[o] + EPS);
        float bias = beta[o] - mean[o] * iv;
        if (o < 64) { iv *= QSCALE; bias *= QSCALE; }
        ivs[t] = iv;
        bss[t] = bias;
    }
    __syncthreads();

    const int warp = t >> 5, lane = t & 31;
    const int wm = warp & 3, wn = warp >> 2;
    const int m0 = wm * 32, n0 = wn * 32;
    const int gp = lane >> 2, tid4 = lane & 3;

    float acc[8][4];
#pragma unroll
    for (int i = 0; i < 8; ++i)
#pragma unroll
        for (int p = 0; p < 4; ++p) acc[i][p] = 0.f;

#pragma unroll
    for (int s = 0; s < 16; ++s) {
        uint32_t a[2][4];
        const float* abase = As + s * 8 + tid4;
#pragma unroll
        for (int mt = 0; mt < 2; ++mt) {
            int r0 = m0 + mt * 16 + gp;
            a[mt][0] = __float_as_uint(abase[r0 * CA_STR]);
            a[mt][1] = __float_as_uint(abase[(r0 + 8) * CA_STR]);
            a[mt][2] = __float_as_uint(abase[r0 * CA_STR + 4]);
            a[mt][3] = __float_as_uint(abase[(r0 + 8) * CA_STR + 4]);
        }
        uint32_t bf[4][2];
        const float* bbase = Bs + (s * 8 + tid4) * CB_STR + n0 + gp;
#pragma unroll
        for (int nt = 0; nt < 4; ++nt) {
            bf[nt][0] = __float_as_uint(bbase[nt * 8]);
            bf[nt][1] = __float_as_uint(bbase[4 * CB_STR + nt * 8]);
        }
#pragma unroll
        for (int mt = 0; mt < 2; ++mt)
#pragma unroll
            for (int nt = 0; nt < 4; ++nt)
                mma_tf32(acc[mt * 4 + nt], a[mt], bf[nt]);
    }

#pragma unroll
    for (int mt = 0; mt < 2; ++mt) {
        int lr0 = m0 + mt * 16 + gp;
        int lr1 = lr0 + 8;
        float iv0 = ivs[lr0], bv0 = bss[lr0];
        float iv1 = ivs[lr1], bv1 = bss[lr1];
        int o0 = o_base + lr0, o1 = o_base + lr1;
        float* d00 = qkv + (size_t)b * 32768 + (o0 & 7) * 4096 + (o0 >> 3) * 128;
        float* d01 = qkv + (size_t)b * 32768 + (o1 & 7) * 4096 + (o1 >> 3) * 128;
#pragma unroll
        for (int nt = 0; nt < 4; ++nt) {
            int d = n0 + nt * 8 + 2 * tid4;
            const float* a4 = acc[mt * 4 + nt];
            float2 s0, s1;
            s0.x = a4[0] * iv0 + bv0; s0.y = a4[1] * iv0 + bv0;
            s1.x = a4[2] * iv1 + bv1; s1.y = a4[3] * iv1 + bv1;
            *reinterpret_cast<float2*>(d00 + d) = s0;
            *reinterpret_cast<float2*>(d01 + d) = s1;
        }
    }
}

// ============================================================================
// Kernel B: attention per (b, h)
// smem layout (float units) — FIXED sizing (atth = 8704 floats):
//  q [8][128] @0, k [8][128] @1024   (psum/pmax + kvred alias @0 later)
//  vh    half[16][136]  @2048   (1088 floats)
//  relqk f32[16][256]   @3136   (4096; relvh half[16][256] aliases after ph.1)
//  atth  half[128][136] @7232   (8704 floats, ends 15936)
//  outv  f32[16][132]   @15936  (2112, ends 18048)
//  cmax/invs [128]      @18048
// total 18176 floats = 72704 B -> 2 CTAs/SM
// ============================================================================
#define ATH_STR  136
#define VH_STR   136
#define SM_Q     0
#define SM_K     1024
#define SM_VH    2048
#define SM_REL   3136
#define SM_ATTH  7232
#define SM_OUTV  15936
#define SM_CMAX  18048
#define SM_TOTAL 18176

__global__ void __launch_bounds__(256, 2)
attn_kernel(const float* __restrict__ qkv, const float* __restrict__ relative,
            float* __restrict__ out)
{
    extern __shared__ float sm[];
    float*  q     = sm + SM_Q;
    float*  k     = sm + SM_K;
    __half* vh    = reinterpret_cast<__half*>(sm + SM_VH);
    float*  relqk = sm + SM_REL;
    __half* atth  = reinterpret_cast<__half*>(sm + SM_ATTH);
    float*  outv  = sm + SM_OUTV;
    float*  cmax  = sm + SM_CMAX;   // colmax, later invs
    float*  psum  = sm + SM_Q;      // pmax/psum alias q/k
    __half* relvh = reinterpret_cast<__half*>(sm + SM_REL);  // after phase 1

    const int t    = threadIdx.x;
    const int bid  = blockIdx.x;
    const int b    = bid >> 3;
    const int h    = bid & 7;
    const int warp = t >> 5, lane = t & 31;
    const int gp   = lane >> 2, tid4 = lane & 3;
    const uint32_t smb = smem_u32(sm);

    // ---------------- phase 0: load q/k, v (fp16, [i][j]), relqk ---------------
    {
        const float* src = qkv + (size_t)b * 32768 + h * 4096;
#pragma unroll
        for (int it = 0; it < 4; ++it) {
            int e4 = t + 256 * it;
            int r  = e4 >> 5;
            int dw = (e4 & 31) * 4;
            float4 val = *reinterpret_cast<const float4*>(src + r * 128 + dw);
            if (r < 8) {
                *reinterpret_cast<float4*>(q + r * 128 + dw) = val;
            } else if (r < 16) {
                *reinterpret_cast<float4*>(k + (r - 8) * 128 + dw) = val;
            } else {
                int i = r - 16;
                __half2 h01 = __floats2half2_rn(val.x, val.y);
                __half2 h23 = __floats2half2_rn(val.z, val.w);
                uint2 u;
                u.x = *reinterpret_cast<uint32_t*>(&h01);
                u.y = *reinterpret_cast<uint32_t*>(&h23);
                *reinterpret_cast<uint2*>(vh + i * VH_STR + dw) = u;
            }
        }
        for (int idx = t; idx < 16 * 255; idx += 256) {
            int c = idx / 255, m = idx - c * 255;
            relqk[c * 256 + m] = relative[idx];
        }
    }
    __syncthreads();

    // ---------------- phase 1: logits (dots + qr + kr) -------------------------
    const int tx = t & 15, ty = t >> 4;
    const int d0l = tx * 8, j0l = ty * 8;
    ull acc[8][4];
    {
        const int base = d0l - j0l + 120;
#pragma unroll
        for (int a = 0; a < 8; ++a)
#pragma unroll
            for (int p = 0; p < 4; ++p) acc[a][p] = 0ULL;

#pragma unroll 2
        for (int i = 0; i < 8; ++i) {
            const float* qi = q + i * 128;
            const float* ki = k + i * 128;
            ull qp[4], kp[4];
            {
                ulonglong2 a0 = *reinterpret_cast<const ulonglong2*>(qi + d0l);
                ulonglong2 a1 = *reinterpret_cast<const ulonglong2*>(qi + d0l + 4);
                qp[0] = a0.x; qp[1] = a0.y; qp[2] = a1.x; qp[3] = a1.y;
                ulonglong2 b0 = *reinterpret_cast<const ulonglong2*>(ki + d0l);
                ulonglong2 b1 = *reinterpret_cast<const ulonglong2*>(ki + d0l + 4);
                kp[0] = b0.x; kp[1] = b0.y; kp[2] = b1.x; kp[3] = b1.y;
            }
            {
                float kj[8];
                *reinterpret_cast<float4*>(kj)     = *reinterpret_cast<const float4*>(ki + j0l);
                *reinterpret_cast<float4*>(kj + 4) = *reinterpret_cast<const float4*>(ki + j0l + 4);
#pragma unroll
                for (int jj = 0; jj < 8; ++jj) {
                    ull kk2 = pk2(kj[jj], kj[jj]);
#pragma unroll
                    for (int p = 0; p < 4; ++p)
                        acc[jj][p] = fma2(qp[p], kk2, acc[jj][p]);
                }
            }
            {
                float wv[16];
                const float* rr = relqk + i * 256 + base;
#pragma unroll
                for (int u = 0; u < 4; ++u)
                    *reinterpret_cast<float4*>(wv + 4 * u) = *reinterpret_cast<const float4*>(rr + 4 * u);
                ull wo[7];
#pragma unroll
                for (int u = 0; u < 7; ++u) wo[u] = pk2(wv[2 * u + 1], wv[2 * u + 2]);
#pragma unroll
                for (int jj = 0; jj < 8; ++jj)
#pragma unroll
                    for (int p = 0; p < 4; ++p) {
                        const int a = 2 * p + 7 - jj;
                        ull pair = (a & 1) ? wo[a >> 1]
                                           : *reinterpret_cast<const ull*>(wv + a);
                        acc[jj][p] = fma2(qp[p], pair, acc[jj][p]);
                    }
            }
            {
                float wv[16];
                const float* rr = relqk + (8 + i) * 256 + base;
#pragma unroll
                for (int u = 0; u < 4; ++u)
                    *reinterpret_cast<float4*>(wv + 4 * u) = *reinterpret_cast<const float4*>(rr + 4 * u);
                ull wo[7];
#pragma unroll
                for (int u = 0; u < 7; ++u) wo[u] = pk2(wv[2 * u + 1], wv[2 * u + 2]);
#pragma unroll
                for (int jj = 0; jj < 8; ++jj)
#pragma unroll
                    for (int p = 0; p < 4; ++p) {
                        const int a = 2 * p + 7 - jj;
                        ull pair = (a & 1) ? wo[a >> 1]
                                           : *reinterpret_cast<const ull*>(wv + a);
                        acc[jj][p] = fma2(kp[p], pair, acc[jj][p]);
                    }
            }
        }
    }

    // ---------------- phase 1b: column max ladder ------------------------------
    {
        float tmax[8];
#pragma unroll
        for (int dd = 0; dd < 8; ++dd) tmax[dd] = -1e30f;
#pragma unroll
        for (int jj = 0; jj < 8; ++jj)
#pragma unroll
            for (int p = 0; p < 4; ++p) {
                float lo, hi;
                upk2(acc[jj][p], lo, hi);
                tmax[2 * p]     = fmaxf(tmax[2 * p], lo);
                tmax[2 * p + 1] = fmaxf(tmax[2 * p + 1], hi);
            }
        __syncthreads();   // q/k reads done; pmax may overwrite
        float4* pm = reinterpret_cast<float4*>(psum + ty * 128 + d0l);
        pm[0] = make_float4(tmax[0], tmax[1], tmax[2], tmax[3]);
        pm[1] = make_float4(tmax[4], tmax[5], tmax[6], tmax[7]);
    }
    __syncthreads();
    if (t < 128) {
        float m = -1e30f;
#pragma unroll
        for (int r = 0; r < 16; ++r) m = fmaxf(m, psum[r * 128 + t]);
        cmax[t] = m;
    }
    __syncthreads();

    // ---------------- phase 1c: exp + fp16 store + sums; relv(fp16) load -------
    {
        float cm[8];
        *reinterpret_cast<float4*>(cm)     = *reinterpret_cast<const float4*>(cmax + d0l);
        *reinterpret_cast<float4*>(cm + 4) = *reinterpret_cast<const float4*>(cmax + d0l + 4);
        float sums[8];
#pragma unroll
        for (int dd = 0; dd < 8; ++dd) sums[dd] = 0.f;
#pragma unroll
        for (int jj = 0; jj < 8; ++jj) {
            __half2 hh[4];
#pragma unroll
            for (int p = 0; p < 4; ++p) {
                float lo, hi;
                upk2(acc[jj][p], lo, hi);
                float e0 = __expf(lo - cm[2 * p]);
                float e1 = __expf(hi - cm[2 * p + 1]);
                sums[2 * p]     += e0;
                sums[2 * p + 1] += e1;
                hh[p] = __floats2half2_rn(e0, e1);
            }
            *reinterpret_cast<uint4*>(atth + (j0l + jj) * ATH_STR + d0l) =
                *reinterpret_cast<uint4*>(hh);
        }
        float4* ps = reinterpret_cast<float4*>(psum + ty * 128 + d0l);
        ps[0] = make_float4(sums[0], sums[1], sums[2], sums[3]);
        ps[1] = make_float4(sums[4], sums[5], sums[6], sums[7]);
        // relv fp16 (relqk fully consumed in phase 1)
        for (int idx = t; idx < 16 * 255; idx += 256) {
            int c = idx / 255, m = idx - c * 255;
            relvh[c * 256 + m] = __float2half(relative[16 * 255 + idx]);
        }
    }
    __syncthreads();
    if (t < 128) {
        float s = 0.f;
#pragma unroll
        for (int r = 0; r < 16; ++r) s += psum[r * 128 + t];
        cmax[t] = 1.0f / s;      // cmax now holds invs
    }
    __syncthreads();

    // ---------------- phase 3a: kv Toeplitz (scalar, fp16 relv windows) --------
    const int i0  = (warp & 3) * 4;
    const int jh  = warp >> 2;
    const int d0  = lane * 4;
    ull acco[4][2];
    {
        const int jb0 = jh * 64;
#pragma unroll
        for (int ii = 0; ii < 4; ++ii) { acco[ii][0] = 0ULL; acco[ii][1] = 0ULL; }

        ull we[4][3], wo[4][3];
        float lastf0[4];
#pragma unroll
        for (int ii = 0; ii < 4; ++ii) {
            const __half* rp = relvh + (i0 + ii) * 256 + (d0 - jb0 + 124);
            uint2 uA = *reinterpret_cast<const uint2*>(rp);
            uint2 uB = *reinterpret_cast<const uint2*>(rp + 4);
            float2 fA = __half22float2(*reinterpret_cast<__half2*>(&uA.x));
            float2 fB = __half22float2(*reinterpret_cast<__half2*>(&uA.y));
            float2 fC = __half22float2(*reinterpret_cast<__half2*>(&uB.x));
            float2 fD = __half22float2(*reinterpret_cast<__half2*>(&uB.y));
            we[ii][0] = pk2(fA.x, fA.y);
            we[ii][1] = pk2(fB.x, fB.y);
            we[ii][2] = pk2(fC.x, fC.y);
            wo[ii][0] = pk2(fA.y, fB.x);
            wo[ii][1] = pk2(fB.y, fC.x);
            wo[ii][2] = pk2(fC.y, fD.x);
            lastf0[ii] = fA.x;
        }

        for (int g = 0; g < 16; ++g) {
            const int jb = jb0 + g * 4;
            if (g > 0) {
                const int baseg = d0 - jb + 124;
#pragma unroll
                for (int ii = 0; ii < 4; ++ii) {
                    we[ii][2] = we[ii][0];
                    wo[ii][2] = wo[ii][0];
                    uint2 uu = *reinterpret_cast<const uint2*>(relvh + (i0 + ii) * 256 + baseg);
                    float2 fA = __half22float2(*reinterpret_cast<__half2*>(&uu.x));
                    float2 fB = __half22float2(*reinterpret_cast<__half2*>(&uu.y));
                    we[ii][0] = pk2(fA.x, fA.y);
                    we[ii][1] = pk2(fB.x, fB.y);
                    wo[ii][0] = pk2(fA.y, fB.x);
                    wo[ii][1] = pk2(fB.y, lastf0[ii]);
                    lastf0[ii] = fA.x;
                }
            }
#pragma unroll
            for (int jj = 0; jj < 4; ++jj) {
                const int j = jb + jj;
                uint2 uu = *reinterpret_cast<const uint2*>(atth + j * ATH_STR + d0);
                float2 f01 = __half22float2(*reinterpret_cast<__half2*>(&uu.x));
                float2 f23 = __half22float2(*reinterpret_cast<__half2*>(&uu.y));
                ull atx = pk2(f01.x, f01.y);
                ull aty = pk2(f23.x, f23.y);
#pragma unroll
                for (int ii = 0; ii < 4; ++ii) {
                    const int o0 = 3 - jj;
                    const int o1 = 5 - jj;
                    ull pr0 = (o0 & 1) ? wo[ii][o0 >> 1] : we[ii][o0 >> 1];
                    ull pr1 = (o1 & 1) ? wo[ii][o1 >> 1] : we[ii][o1 >> 1];
                    acco[ii][0] = fma2(atx, pr0, acco[ii][0]);
                    acco[ii][1] = fma2(aty, pr1, acco[ii][1]);
                }
            }
        }

        // jh=1 warps deposit kv partials into kvred (q/k region, dead)
        ull* red = reinterpret_cast<ull*>(sm + SM_Q);
        if (jh == 1) {
#pragma unroll
            for (int ii = 0; ii < 4; ++ii) {
                red[(i0 + ii) * 64 + lane * 2 + 0] = acco[ii][0];
                red[(i0 + ii) * 64 + lane * 2 + 1] = acco[ii][1];
            }
        }
    }

    // ---------------- phase 3b: out_v = attn(fp16) . v(fp16) via HMMA ----------
    {
        const int m0 = warp * 16;                  // 16 d rows per warp
        const uint32_t atth_b = smb + SM_ATTH * 4;
        const uint32_t vh_b   = smb + SM_VH * 4;

        const int arow = (lane & 7) + ((lane >> 4) << 3);        // k-row offset
        const int acol = m0 + (((lane >> 3) & 1) << 3);          // m offset (halves)
        uint32_t a_addr = atth_b + (uint32_t)(arow * ATH_STR + acol) * 2;

        const int bl  = lane & 15;
        const int bn  = bl & 7;
        const int bk8 = ((bl >> 3) & 1) * 8;
        uint32_t b_addr0 = vh_b + (uint32_t)(bn * VH_STR + bk8) * 2;        // i 0..7
        uint32_t b_addr1 = vh_b + (uint32_t)((8 + bn) * VH_STR + bk8) * 2;  // i 8..15

        float c0[4] = {0.f, 0.f, 0.f, 0.f};
        float c1[4] = {0.f, 0.f, 0.f, 0.f};
#pragma unroll
        for (int ks = 0; ks < 8; ++ks) {
            uint32_t a[4];
            ldsm_x4_t(a[0], a[1], a[2], a[3], a_addr + ks * (16 * ATH_STR * 2));
            uint32_t b0[2], b1[2];
            ldsm_x2(b0[0], b0[1], b_addr0 + ks * 32);
            ldsm_x2(b1[0], b1[1], b_addr1 + ks * 32);
            mma_f16(c0, a, b0);
            mma_f16(c1, a, b1);
        }
        // store outv[i][d] (stride 132: conflict-free STS.32)
        const int dA = m0 + gp, dB = m0 + gp + 8;
        outv[(2 * tid4)     * 132 + dA] = c0[0];
        outv[(2 * tid4 + 1) * 132 + dA] = c0[1];
        outv[(2 * tid4)     * 132 + dB] = c0[2];
        outv[(2 * tid4 + 1) * 132 + dB] = c0[3];
        outv[(8 + 2 * tid4)     * 132 + dA] = c1[0];
        outv[(8 + 2 * tid4 + 1) * 132 + dA] = c1[1];
        outv[(8 + 2 * tid4)     * 132 + dB] = c1[2];
        outv[(8 + 2 * tid4 + 1) * 132 + dB] = c1[3];
    }
    __syncthreads();   // kvred + outv complete

    // ---------------- phase 4: combine + normalize + store ---------------------
    if (jh == 0) {
        const ull* red = reinterpret_cast<const ull*>(sm + SM_Q);
        float4 iv4 = *reinterpret_cast<const float4*>(cmax + d0);
        float* ob = out + (size_t)b * 16384 + h * 2048;
#pragma unroll
        for (int ii = 0; ii < 4; ++ii) {
            ull s0 = add2(acco[ii][0], red[(i0 + ii) * 64 + lane * 2 + 0]);
            ull s1 = add2(acco[ii][1], red[(i0 + ii) * 64 + lane * 2 + 1]);
            float4 ov = *reinterpret_cast<const float4*>(outv + (i0 + ii) * 132 + d0);
            float4 r;
            upk2(s0, r.x, r.y);
            upk2(s1, r.z, r.w);
            r.x = (r.x + ov.x) * iv4.x;
            r.y = (r.y + ov.y) * iv4.y;
            r.z = (r.z + ov.z) * iv4.z;
            r.w = (r.w + ov.w) * iv4.w;
            *reinterpret_cast<float4*>(ob + (i0 + ii) * 128 + d0) = r;
        }
    }
}

// ============================================================================
extern "C" void kernel_launch(void* const* d_in, const int* in_sizes, int n_in,
                              void* d_out, int out_size) {
    const float* x        = (const float*)d_in[0];
    const float* W        = (const float*)d_in[1];
    const float* gamma    = (const float*)d_in[2];
    const float* beta     = (const float*)d_in[3];
    const float* mean     = (const float*)d_in[4];
    const float* var      = (const float*)d_in[5];
    const float* relative = (const float*)d_in[6];
    float* out = (float*)d_out;

    int nb = in_sizes[0] / (INC * DIM);

    float* scratch;
    cudaGetSymbolAddress((void**)&scratch, g_qkv);

    const int smemA = CV_TOT * (int)sizeof(float);     // 138240
    const int smemB = SM_TOTAL * (int)sizeof(float);   // 72704
    cudaFuncSetAttribute(conv_bn_mma_kernel, cudaFuncAttributeMaxDynamicSharedMemorySize, smemA);
    cudaFuncSetAttribute(attn_kernel,        cudaFuncAttributeMaxDynamicSharedMemorySize, smemB);

    conv_bn_mma_kernel<<<nb * 2, 512, smemA>>>(x, W, gamma, beta, mean, var, scratch);
    attn_kernel<<<nb * HEADS, 256, smemB>>>(scratch, relative, out);
}